// round 13
// baseline (speedup 1.0000x reference)
#include <cuda_runtime.h>
#include <cuda_bf16.h>
#include <cstdint>

// Problem constants
#define BB 4
#define SS 2048
#define DD 512
#define HH 8
#define HDIM 64
#define MTOT (BB*SS)          // 8192 rows

// Pre-split operands (packed bf16 hi/lo pairs as uint32)
__device__ uint32_t gx_h[MTOT*DD/2];           // x split
__device__ uint32_t gx_l[MTOT*DD/2];
__device__ uint32_t gw_h[3*DD*DD/2];           // Wq/Wk/Wv split
__device__ uint32_t gw_l[3*DD*DD/2];
__device__ uint32_t gq_h[MTOT*DD/2];           // projected q/k split
__device__ uint32_t gq_l[MTOT*DD/2];
__device__ uint32_t gk_h[MTOT*DD/2];
__device__ uint32_t gk_l[MTOT*DD/2];
__device__ uint32_t gvt_h[BB*HH*HDIM*(SS/2)];  // V^T split [bh][dim][tok-pair]
__device__ uint32_t gvt_l[BB*HH*HDIM*(SS/2)];

// q pre-scale: (1/sqrt(64)) * log2(e)  -> attention uses ex2.approx directly
#define QSCALE 0.1803368801111204f

// ===========================================================================
// Helpers
// ===========================================================================
__device__ __forceinline__ uint32_t pack_bf16(__nv_bfloat16 x, __nv_bfloat16 y) {
    return (uint32_t)__bfloat16_as_ushort(x) | ((uint32_t)__bfloat16_as_ushort(y) << 16);
}
__device__ __forceinline__ void split2(float2 v, uint32_t& hi, uint32_t& lo) {
    __nv_bfloat16 hx = __float2bfloat16(v.x), hy = __float2bfloat16(v.y);
    float rx = v.x - __bfloat162float(hx);
    float ry = v.y - __bfloat162float(hy);
    hi = pack_bf16(hx, hy);
    lo = pack_bf16(__float2bfloat16(rx), __float2bfloat16(ry));
}
__device__ __forceinline__ float ex2f(float x) {
    float y;
    asm("ex2.approx.f32 %0, %1;" : "=f"(y) : "f"(x));
    return y;
}
__device__ __forceinline__ void mma16816(float c[4], const uint32_t a[4],
                                         uint32_t b0, uint32_t b1) {
    asm volatile(
        "mma.sync.aligned.m16n8k16.row.col.f32.bf16.bf16.f32 "
        "{%0,%1,%2,%3}, {%4,%5,%6,%7}, {%8,%9}, {%0,%1,%2,%3};"
        : "+f"(c[0]), "+f"(c[1]), "+f"(c[2]), "+f"(c[3])
        : "r"(a[0]), "r"(a[1]), "r"(a[2]), "r"(a[3]), "r"(b0), "r"(b1));
}
#define LDSM4(R0,R1,R2,R3,ADDR) \
    asm volatile("ldmatrix.sync.aligned.m8n8.x4.shared.b16 {%0,%1,%2,%3}, [%4];" \
        : "=r"(R0),"=r"(R1),"=r"(R2),"=r"(R3) : "r"(ADDR))
#define CP_ASYNC16(DST, SRC) \
    asm volatile("cp.async.cg.shared.global [%0], [%1], 16;" :: "r"(DST), "l"(SRC))
#define CP_COMMIT() asm volatile("cp.async.commit_group;")

// ===========================================================================
// Kernel 0a/0b: pre-split x and W (float4 = 2 pairs per thread)
// ===========================================================================
__global__ __launch_bounds__(256) void split_x_kernel(const float* __restrict__ x)
{
    int idx = blockIdx.x * 256 + threadIdx.x;       // quad index (4 floats)
    float4 v = *(const float4*)&x[(size_t)idx * 4];
    uint2 hi, lo;
    split2(make_float2(v.x, v.y), hi.x, lo.x);
    split2(make_float2(v.z, v.w), hi.y, lo.y);
    *(uint2*)&gx_h[(size_t)idx * 2] = hi;
    *(uint2*)&gx_l[(size_t)idx * 2] = lo;
}
__global__ __launch_bounds__(256) void split_w_kernel(
    const float* __restrict__ Wq, const float* __restrict__ Wk,
    const float* __restrict__ Wv)
{
    const float* W = (blockIdx.y == 0) ? Wq : (blockIdx.y == 1) ? Wk : Wv;
    int idx = blockIdx.x * 256 + threadIdx.x;       // quad index
    float4 v = *(const float4*)&W[(size_t)idx * 4];
    uint2 hi, lo;
    split2(make_float2(v.x, v.y), hi.x, lo.x);
    split2(make_float2(v.z, v.w), hi.y, lo.y);
    size_t o = (size_t)blockIdx.y * (DD * DD / 2) + (size_t)idx * 2;
    *(uint2*)&gw_h[o] = hi;
    *(uint2*)&gw_l[o] = lo;
}

// ===========================================================================
// Kernel A: QKV GEMM on warp MMA, split-bf16 3-pass.
// sel==2 (V): epilogue transposes in-CTA and writes split V^T directly.
// ===========================================================================
#define GBM 128
#define GBN 64
#define GBK 64

__global__ __launch_bounds__(256) void qkv_mma_gemm_kernel(
    const float* __restrict__ bq, const float* __restrict__ bk,
    const float* __restrict__ bv)
{
    extern __shared__ uint8_t gsm[];
    const uint32_t sb = (uint32_t)__cvta_generic_to_shared(gsm);
    const int tid = threadIdx.x;
    const int wid = tid >> 5, lane = tid & 31;
    const int sel = blockIdx.z;
    const int nBase = blockIdx.x * GBN;
    const int mBase = blockIdx.y * GBM;
    const int m0 = (wid >> 1) * 32;
    const int n0 = (wid & 1) * 32;

    const uint32_t* WH = gw_h + (size_t)sel * (DD * DD / 2);
    const uint32_t* WL = gw_l + (size_t)sel * (DD * DD / 2);
    const float* bias = (sel == 0) ? bq : (sel == 1) ? bk : bv;

    auto stage = [&](int buf, int kk) {
        const uint32_t bufo = (uint32_t)(buf * 49152);
        #pragma unroll
        for (int j = 0; j < 8; j++) {                 // A
            int c = tid + j * 256;
            int arr = c >> 10, wi = c & 1023;
            int r = wi >> 3, i = wi & 7;
            uint32_t dst = sb + bufo + (uint32_t)(arr * 16384 + r * 128)
                           + (uint32_t)((i * 16) ^ ((r & 7) << 4));
            const uint32_t* src = (arr == 0 ? gx_h : gx_l)
                                  + ((size_t)(mBase + r) * 256 + kk * 32 + i * 4);
            CP_ASYNC16(dst, src);
        }
        #pragma unroll
        for (int j = 0; j < 4; j++) {                 // B
            int c = tid + j * 256;
            int arr = c >> 9, wi = c & 511;
            int r = wi >> 3, i = wi & 7;
            uint32_t dst = sb + bufo + 32768u + (uint32_t)(arr * 8192 + r * 128)
                           + (uint32_t)((i * 16) ^ ((r & 7) << 4));
            const uint32_t* src = (arr == 0 ? WH : WL)
                                  + ((size_t)(nBase + r) * 256 + kk * 32 + i * 4);
            CP_ASYNC16(dst, src);
        }
    };

    float c[2][4][4];
    #pragma unroll
    for (int mt = 0; mt < 2; mt++)
        #pragma unroll
        for (int t = 0; t < 4; t++)
            #pragma unroll
            for (int i = 0; i < 4; i++) c[mt][t][i] = 0.0f;

    const int arow  = (((lane >> 3) & 1) << 3) | (lane & 7);
    const int ahalf = lane >> 4;
    const uint32_t aswz = (uint32_t)((arow & 7) << 4);
    const int brow  = ((lane >> 4) << 3) | (lane & 7);
    const int bosel = (lane >> 3) & 1;
    const uint32_t bswz = (uint32_t)((brow & 7) << 4);

    stage(0, 0);
    CP_COMMIT();

    #pragma unroll 1
    for (int kk = 0; kk < DD / GBK; kk++) {
        const int buf = kk & 1;
        if (kk + 1 < DD / GBK) {
            stage(buf ^ 1, kk + 1);
            CP_COMMIT();
            asm volatile("cp.async.wait_group 1;");
        } else {
            asm volatile("cp.async.wait_group 0;");
        }
        __syncthreads();

        const uint32_t Ah = sb + (uint32_t)(buf * 49152);
        const uint32_t Al = Ah + 16384u;
        const uint32_t Bh = Ah + 32768u;
        const uint32_t Bl = Bh + 8192u;

        #pragma unroll
        for (int kc = 0; kc < 4; kc++) {
            const uint32_t acol = (uint32_t)(((2 * kc + ahalf) * 16)) ^ aswz;
            const uint32_t bcol = (uint32_t)(((2 * kc + bosel) * 16)) ^ bswz;
            uint32_t ah[2][4], al[2][4], bh[2][4], bl[2][4];
            #pragma unroll
            for (int mt = 0; mt < 2; mt++) {
                uint32_t ro = (uint32_t)((m0 + mt * 16 + arow) * 128);
                LDSM4(ah[mt][0], ah[mt][1], ah[mt][2], ah[mt][3], Ah + ro + acol);
                LDSM4(al[mt][0], al[mt][1], al[mt][2], al[mt][3], Al + ro + acol);
            }
            #pragma unroll
            for (int gp = 0; gp < 2; gp++) {
                uint32_t ro = (uint32_t)((n0 + gp * 16 + brow) * 128);
                LDSM4(bh[gp][0], bh[gp][1], bh[gp][2], bh[gp][3], Bh + ro + bcol);
                LDSM4(bl[gp][0], bl[gp][1], bl[gp][2], bl[gp][3], Bl + ro + bcol);
            }
            #pragma unroll
            for (int mt = 0; mt < 2; mt++)
                #pragma unroll
                for (int t = 0; t < 4; t++) {
                    const int gp = t >> 1, pv = (t & 1) * 2;
                    mma16816(c[mt][t], ah[mt], bh[gp][pv], bh[gp][pv + 1]);
                    mma16816(c[mt][t], ah[mt], bl[gp][pv], bl[gp][pv + 1]);
                    mma16816(c[mt][t], al[mt], bh[gp][pv], bh[gp][pv + 1]);
                }
        }
        __syncthreads();
    }

    const int crow = lane >> 2;
    const int ccol = (lane & 3) * 2;

    if (sel == 2) {
        // ---- V epilogue: bias add -> smem fp32 tile -> transposed split ----
        float (*vt)[65] = (float(*)[65])gsm;   // 128 x 65 floats (33 KB)
        #pragma unroll
        for (int mt = 0; mt < 2; mt++)
            #pragma unroll
            for (int t = 0; t < 4; t++) {
                const int rloc = m0 + mt * 16 + crow;
                const int cloc = n0 + t * 8 + ccol;
                const float b0 = bias[nBase + cloc], b1 = bias[nBase + cloc + 1];
                vt[rloc][cloc]     = c[mt][t][0] + b0;
                vt[rloc][cloc + 1] = c[mt][t][1] + b1;
                vt[rloc + 8][cloc]     = c[mt][t][2] + b0;
                vt[rloc + 8][cloc + 1] = c[mt][t][3] + b1;
            }
        __syncthreads();
        const int b  = mBase / SS;
        const int s0 = mBase % SS;
        const int bh = b * HH + (nBase / HDIM);
        #pragma unroll
        for (int i = 0; i < 16; i++) {
            int p  = tid + i * 256;            // 0..4095
            int dl = p >> 6;                   // dim 0..63
            int pp = p & 63;                   // token pair 0..63
            uint32_t hi, lo;
            split2(make_float2(vt[2 * pp][dl], vt[2 * pp + 1][dl]), hi, lo);
            size_t idx = (size_t)(bh * HDIM + dl) * (SS / 2) + (s0 >> 1) + pp;
            gvt_h[idx] = hi;
            gvt_l[idx] = lo;
        }
    } else {
        const float scale = (sel == 0) ? QSCALE : 1.0f;
        uint32_t* oh = (sel == 0) ? gq_h : gk_h;
        uint32_t* ol = (sel == 0) ? gq_l : gk_l;
        #pragma unroll
        for (int mt = 0; mt < 2; mt++)
            #pragma unroll
            for (int t = 0; t < 4; t++) {
                const int row = mBase + m0 + mt * 16 + crow;
                const int col = nBase + n0 + t * 8 + ccol;
                const float b0 = bias[col], b1 = bias[col + 1];
                float2 v0 = make_float2((c[mt][t][0] + b0) * scale,
                                        (c[mt][t][1] + b1) * scale);
                float2 v1 = make_float2((c[mt][t][2] + b0) * scale,
                                        (c[mt][t][3] + b1) * scale);
                size_t p0 = (size_t)row * 256 + col / 2;
                size_t p1 = (size_t)(row + 8) * 256 + col / 2;
                split2(v0, oh[p0], ol[p0]);
                split2(v1, oh[p1], ol[p1]);
            }
    }
}

// ===========================================================================
// Kernel B: warp-MMA flash attention (128 thr, q-tile 64, no online max,
// single-MUFU ex2.approx with log2e pre-folded into q).
// Staging addresses hoisted out of the tile loop.
// ===========================================================================
#define KT 64
#define NT (SS / KT)

__global__ __launch_bounds__(128) void attn_mma_kernel(float* __restrict__ out)
{
    extern __shared__ uint8_t dynsmem[];
    const int tid  = threadIdx.x;
    const int w    = tid >> 5;
    const int lane = tid & 31;
    const int r0   = lane >> 2;
    const int c0   = (lane & 3) * 2;
    const int qt = blockIdx.x, h = blockIdx.y, b = blockIdx.z;
    const int bh = b * HH + h;
    const int qr = qt * 64 + w * 16 + r0;

    const uint32_t smem_base = (uint32_t)__cvta_generic_to_shared(dynsmem);

    uint32_t aQh[4][4], aQl[4][4];
    {
        const size_t row0 = (size_t)(b * SS + qr) * 256 + h * 32;
        const size_t row8 = row0 + 8 * 256;
        #pragma unroll
        for (int kc = 0; kc < 4; kc++) {
            int idx = kc * 8 + (lane & 3);
            aQh[kc][0] = gq_h[row0 + idx];     aQl[kc][0] = gq_l[row0 + idx];
            aQh[kc][1] = gq_h[row8 + idx];     aQl[kc][1] = gq_l[row8 + idx];
            aQh[kc][2] = gq_h[row0 + idx + 4]; aQl[kc][2] = gq_l[row0 + idx + 4];
            aQh[kc][3] = gq_h[row8 + idx + 4]; aQl[kc][3] = gq_l[row8 + idx + 4];
        }
    }

    // ---- Hoisted per-thread staging offsets (4 chunk slots) ----
    uint32_t kdst[4];       // dst offset within one array (same for K and V)
    size_t   ksrc[4];       // element offset into gk_* (advances by KT*256/tile)
    size_t   vsrc[4];       // element offset into gvt_* (advances by 32/tile)
    #pragma unroll
    for (int cc = 0; cc < 4; cc++) {
        int cch = tid + cc * 128;
        int r = cch >> 3, i = cch & 7;
        kdst[cc] = (uint32_t)(r * 128) + (uint32_t)((i * 16) ^ ((r & 7) << 4));
        ksrc[cc] = (size_t)(b * SS + r) * 256 + h * 32 + i * 4;
        vsrc[cc] = (size_t)(bh * HDIM + r) * (SS / 2) + i * 4;
    }

    auto stage = [&](int buf, int t) {
        const uint32_t kb = smem_base + (uint32_t)(buf * 16384);
        const uint32_t vb = kb + 32768u;
        const size_t kadv = (size_t)t * (KT * 256);
        const size_t vadv = (size_t)t * 32;
        #pragma unroll
        for (int cc = 0; cc < 4; cc++) {
            const size_t ks = ksrc[cc] + kadv;
            const size_t vs = vsrc[cc] + vadv;
            CP_ASYNC16(kb + kdst[cc],         gk_h + ks);
            CP_ASYNC16(kb + 8192u + kdst[cc], gk_l + ks);
            CP_ASYNC16(vb + kdst[cc],         gvt_h + vs);
            CP_ASYNC16(vb + 8192u + kdst[cc], gvt_l + vs);
        }
    };

    float o[8][4];
    #pragma unroll
    for (int dt = 0; dt < 8; dt++)
        #pragma unroll
        for (int i = 0; i < 4; i++) o[dt][i] = 0.0f;
    float lA0 = 0.0f, lA1 = 0.0f, lB0 = 0.0f, lB1 = 0.0f;

    const int lrow = ((lane >> 4) << 3) + (lane & 7);
    const int osel = (lane >> 3) & 1;
    const uint32_t lswz = (uint32_t)((lrow & 7) << 4);

    stage(0, 0);
    CP_COMMIT();

    for (int t = 0; t < NT; t++) {
        const int buf = t & 1;
        if (t + 1 < NT) {
            stage(buf ^ 1, t + 1);
            CP_COMMIT();
            asm volatile("cp.async.wait_group 1;");
        } else {
            asm volatile("cp.async.wait_group 0;");
        }
        __syncthreads();

        const uint32_t Kh_b = smem_base + (uint32_t)(buf * 16384);
        const uint32_t Kl_b = Kh_b + 8192u;
        const uint32_t Vh_b = Kh_b + 32768u;
        const uint32_t Vl_b = Vh_b + 8192u;

        // ---- Scores ----
        float sc[8][4];
        #pragma unroll
        for (int gp = 0; gp < 4; gp++) {
            float s0[4] = {0,0,0,0}, s1[4] = {0,0,0,0};
            const uint32_t rbase = (uint32_t)((gp * 16 + lrow) * 128);
            #pragma unroll
            for (int kc = 0; kc < 4; kc++) {
                const uint32_t boff = (uint32_t)(((2*kc + osel) * 16)) ^ lswz;
                uint32_t h0,h1,h2,h3, l0,l1,l2,l3;
                LDSM4(h0,h1,h2,h3, Kh_b + rbase + boff);
                LDSM4(l0,l1,l2,l3, Kl_b + rbase + boff);
                mma16816(s0, aQh[kc], h0, h1);
                mma16816(s0, aQh[kc], l0, l1);
                mma16816(s0, aQl[kc], h0, h1);
                mma16816(s1, aQh[kc], h2, h3);
                mma16816(s1, aQh[kc], l2, l3);
                mma16816(s1, aQl[kc], h2, h3);
            }
            #pragma unroll
            for (int i = 0; i < 4; i++) { sc[2*gp][i] = s0[i]; sc[2*gp+1][i] = s1[i]; }
        }

        // ---- ex2 (single MUFU; log2e folded into q) + dual partial sums ----
        #pragma unroll
        for (int nt = 0; nt < 8; nt++) {
            sc[nt][0] = ex2f(sc[nt][0]); lA0 += sc[nt][0];
            sc[nt][1] = ex2f(sc[nt][1]); lA1 += sc[nt][1];
            sc[nt][2] = ex2f(sc[nt][2]); lB0 += sc[nt][2];
            sc[nt][3] = ex2f(sc[nt][3]); lB1 += sc[nt][3];
        }

        // ---- Repack P into A-fragments (hi/lo) ----
        uint32_t aPh[4][4], aPl[4][4];
        #pragma unroll
        for (int kc = 0; kc < 4; kc++) {
            split2(make_float2(sc[2*kc  ][0], sc[2*kc  ][1]), aPh[kc][0], aPl[kc][0]);
            split2(make_float2(sc[2*kc  ][2], sc[2*kc  ][3]), aPh[kc][1], aPl[kc][1]);
            split2(make_float2(sc[2*kc+1][0], sc[2*kc+1][1]), aPh[kc][2], aPl[kc][2]);
            split2(make_float2(sc[2*kc+1][2], sc[2*kc+1][3]), aPh[kc][3], aPl[kc][3]);
        }

        // ---- O += P*V ----
        #pragma unroll
        for (int dtp = 0; dtp < 4; dtp++) {
            const uint32_t rbase = (uint32_t)((dtp * 16 + lrow) * 128);
            #pragma unroll
            for (int kc = 0; kc < 4; kc++) {
                const uint32_t boff = (uint32_t)(((2*kc + osel) * 16)) ^ lswz;
                uint32_t v0,v1,v2,v3, w0,w1,w2,w3;
                LDSM4(v0,v1,v2,v3, Vh_b + rbase + boff);
                LDSM4(w0,w1,w2,w3, Vl_b + rbase + boff);
                mma16816(o[2*dtp],   aPh[kc], v0, v1);
                mma16816(o[2*dtp],   aPh[kc], w0, w1);
                mma16816(o[2*dtp],   aPl[kc], v0, v1);
                mma16816(o[2*dtp+1], aPh[kc], v2, v3);
                mma16816(o[2*dtp+1], aPh[kc], w2, w3);
                mma16816(o[2*dtp+1], aPl[kc], v2, v3);
            }
        }
        __syncthreads();
    }

    // ---- Final l reduction across the quad, then normalize + store ----
    float lA = lA0 + lA1, lB = lB0 + lB1;
    lA += __shfl_xor_sync(0xffffffff, lA, 1);
    lA += __shfl_xor_sync(0xffffffff, lA, 2);
    lB += __shfl_xor_sync(0xffffffff, lB, 1);
    lB += __shfl_xor_sync(0xffffffff, lB, 2);
    const float ivA = 1.0f / lA, ivB = 1.0f / lB;
    #pragma unroll
    for (int dt = 0; dt < 8; dt++) {
        float2 t0 = make_float2(o[dt][0] * ivA, o[dt][1] * ivA);
        float2 t1 = make_float2(o[dt][2] * ivB, o[dt][3] * ivB);
        *(float2*)&out[((size_t)(b*SS + qr    ))*DD + h*HDIM + dt*8 + c0] = t0;
        *(float2*)&out[((size_t)(b*SS + qr + 8))*DD + h*HDIM + dt*8 + c0] = t1;
    }
}

// ===========================================================================
extern "C" void kernel_launch(void* const* d_in, const int* in_sizes, int n_in,
                              void* d_out, int out_size)
{
    const float* x  = (const float*)d_in[0];
    const float* Wq = (const float*)d_in[1];
    const float* bq = (const float*)d_in[2];
    const float* Wk = (const float*)d_in[3];
    const float* bk = (const float*)d_in[4];
    const float* Wv = (const float*)d_in[5];
    const float* bv = (const float*)d_in[6];
    float* out = (float*)d_out;

    split_x_kernel<<<MTOT * DD / 4 / 256, 256>>>(x);
    split_w_kernel<<<dim3(DD * DD / 4 / 256, 3), 256>>>(Wq, Wk, Wv);

    cudaFuncSetAttribute(qkv_mma_gemm_kernel,
                         cudaFuncAttributeMaxDynamicSharedMemorySize, 98304);
    dim3 gg(DD / GBN, MTOT / GBM, 3);
    qkv_mma_gemm_kernel<<<gg, 256, 98304>>>(bq, bk, bv);

    cudaFuncSetAttribute(attn_mma_kernel,
                         cudaFuncAttributeMaxDynamicSharedMemorySize, 65536);
    dim3 g2(SS / 64, HH, BB);
    attn_mma_kernel<<<g2, 128, 65536>>>(out);
}

// round 15
// speedup vs baseline: 1.1271x; 1.1271x over previous
#include <cuda_runtime.h>
#include <cuda_bf16.h>
#include <cstdint>

// Problem constants
#define BB 4
#define SS 2048
#define DD 512
#define HH 8
#define HDIM 64
#define MTOT (BB*SS)          // 8192 rows

// Pre-split operands (packed bf16 hi/lo pairs as uint32)
__device__ uint32_t gx_h[MTOT*DD/2];           // x split
__device__ uint32_t gx_l[MTOT*DD/2];
__device__ uint32_t gw_h[3*DD*DD/2];           // Wq/Wk/Wv split
__device__ uint32_t gw_l[3*DD*DD/2];
__device__ uint32_t gq_h[MTOT*DD/2];           // projected q/k split
__device__ uint32_t gq_l[MTOT*DD/2];
__device__ uint32_t gk_h[MTOT*DD/2];
__device__ uint32_t gk_l[MTOT*DD/2];
__device__ uint32_t gvt_h[BB*HH*HDIM*(SS/2)];  // V^T split [bh][dim][tok-pair]
__device__ uint32_t gvt_l[BB*HH*HDIM*(SS/2)];

// q pre-scale: (1/sqrt(64)) * log2(e)  -> attention uses ex2.approx directly
#define QSCALE 0.1803368801111204f

// ===========================================================================
// Helpers
// ===========================================================================
__device__ __forceinline__ uint32_t pack_bf16(__nv_bfloat16 x, __nv_bfloat16 y) {
    return (uint32_t)__bfloat16_as_ushort(x) | ((uint32_t)__bfloat16_as_ushort(y) << 16);
}
__device__ __forceinline__ void split2(float2 v, uint32_t& hi, uint32_t& lo) {
    __nv_bfloat16 hx = __float2bfloat16(v.x), hy = __float2bfloat16(v.y);
    float rx = v.x - __bfloat162float(hx);
    float ry = v.y - __bfloat162float(hy);
    hi = pack_bf16(hx, hy);
    lo = pack_bf16(__float2bfloat16(rx), __float2bfloat16(ry));
}
__device__ __forceinline__ float ex2f(float x) {
    float y;
    asm("ex2.approx.f32 %0, %1;" : "=f"(y) : "f"(x));
    return y;
}
__device__ __forceinline__ void mma16816(float c[4], const uint32_t a[4],
                                         uint32_t b0, uint32_t b1) {
    asm volatile(
        "mma.sync.aligned.m16n8k16.row.col.f32.bf16.bf16.f32 "
        "{%0,%1,%2,%3}, {%4,%5,%6,%7}, {%8,%9}, {%0,%1,%2,%3};"
        : "+f"(c[0]), "+f"(c[1]), "+f"(c[2]), "+f"(c[3])
        : "r"(a[0]), "r"(a[1]), "r"(a[2]), "r"(a[3]), "r"(b0), "r"(b1));
}
#define LDSM4(R0,R1,R2,R3,ADDR) \
    asm volatile("ldmatrix.sync.aligned.m8n8.x4.shared.b16 {%0,%1,%2,%3}, [%4];" \
        : "=r"(R0),"=r"(R1),"=r"(R2),"=r"(R3) : "r"(ADDR))
#define CP_ASYNC16(DST, SRC) \
    asm volatile("cp.async.cg.shared.global [%0], [%1], 16;" :: "r"(DST), "l"(SRC))
#define CP_COMMIT() asm volatile("cp.async.commit_group;")

// ===========================================================================
// Kernel 0a/0b: pre-split x and W (float4 = 2 pairs per thread)
// ===========================================================================
__global__ __launch_bounds__(256) void split_x_kernel(const float* __restrict__ x)
{
    int idx = blockIdx.x * 256 + threadIdx.x;       // quad index (4 floats)
    float4 v = *(const float4*)&x[(size_t)idx * 4];
    uint2 hi, lo;
    split2(make_float2(v.x, v.y), hi.x, lo.x);
    split2(make_float2(v.z, v.w), hi.y, lo.y);
    *(uint2*)&gx_h[(size_t)idx * 2] = hi;
    *(uint2*)&gx_l[(size_t)idx * 2] = lo;
}
__global__ __launch_bounds__(256) void split_w_kernel(
    const float* __restrict__ Wq, const float* __restrict__ Wk,
    const float* __restrict__ Wv)
{
    const float* W = (blockIdx.y == 0) ? Wq : (blockIdx.y == 1) ? Wk : Wv;
    int idx = blockIdx.x * 256 + threadIdx.x;       // quad index
    float4 v = *(const float4*)&W[(size_t)idx * 4];
    uint2 hi, lo;
    split2(make_float2(v.x, v.y), hi.x, lo.x);
    split2(make_float2(v.z, v.w), hi.y, lo.y);
    size_t o = (size_t)blockIdx.y * (DD * DD / 2) + (size_t)idx * 2;
    *(uint2*)&gw_h[o] = hi;
    *(uint2*)&gw_l[o] = lo;
}

// ===========================================================================
// Kernel A: QKV GEMM on warp MMA, split-bf16 3-pass.
// sel==2 (V): epilogue transposes in-CTA and writes split V^T directly.
// ===========================================================================
#define GBM 128
#define GBN 64
#define GBK 64

__global__ __launch_bounds__(256) void qkv_mma_gemm_kernel(
    const float* __restrict__ bq, const float* __restrict__ bk,
    const float* __restrict__ bv)
{
    extern __shared__ uint8_t gsm[];
    const uint32_t sb = (uint32_t)__cvta_generic_to_shared(gsm);
    const int tid = threadIdx.x;
    const int wid = tid >> 5, lane = tid & 31;
    const int sel = blockIdx.z;
    const int nBase = blockIdx.x * GBN;
    const int mBase = blockIdx.y * GBM;
    const int m0 = (wid >> 1) * 32;
    const int n0 = (wid & 1) * 32;

    const uint32_t* WH = gw_h + (size_t)sel * (DD * DD / 2);
    const uint32_t* WL = gw_l + (size_t)sel * (DD * DD / 2);
    const float* bias = (sel == 0) ? bq : (sel == 1) ? bk : bv;

    auto stage = [&](int buf, int kk) {
        const uint32_t bufo = (uint32_t)(buf * 49152);
        #pragma unroll
        for (int j = 0; j < 8; j++) {                 // A
            int c = tid + j * 256;
            int arr = c >> 10, wi = c & 1023;
            int r = wi >> 3, i = wi & 7;
            uint32_t dst = sb + bufo + (uint32_t)(arr * 16384 + r * 128)
                           + (uint32_t)((i * 16) ^ ((r & 7) << 4));
            const uint32_t* src = (arr == 0 ? gx_h : gx_l)
                                  + ((size_t)(mBase + r) * 256 + kk * 32 + i * 4);
            CP_ASYNC16(dst, src);
        }
        #pragma unroll
        for (int j = 0; j < 4; j++) {                 // B
            int c = tid + j * 256;
            int arr = c >> 9, wi = c & 511;
            int r = wi >> 3, i = wi & 7;
            uint32_t dst = sb + bufo + 32768u + (uint32_t)(arr * 8192 + r * 128)
                           + (uint32_t)((i * 16) ^ ((r & 7) << 4));
            const uint32_t* src = (arr == 0 ? WH : WL)
                                  + ((size_t)(nBase + r) * 256 + kk * 32 + i * 4);
            CP_ASYNC16(dst, src);
        }
    };

    float c[2][4][4];
    #pragma unroll
    for (int mt = 0; mt < 2; mt++)
        #pragma unroll
        for (int t = 0; t < 4; t++)
            #pragma unroll
            for (int i = 0; i < 4; i++) c[mt][t][i] = 0.0f;

    const int arow  = (((lane >> 3) & 1) << 3) | (lane & 7);
    const int ahalf = lane >> 4;
    const uint32_t aswz = (uint32_t)((arow & 7) << 4);
    const int brow  = ((lane >> 4) << 3) | (lane & 7);
    const int bosel = (lane >> 3) & 1;
    const uint32_t bswz = (uint32_t)((brow & 7) << 4);

    stage(0, 0);
    CP_COMMIT();

    #pragma unroll 1
    for (int kk = 0; kk < DD / GBK; kk++) {
        const int buf = kk & 1;
        if (kk + 1 < DD / GBK) {
            stage(buf ^ 1, kk + 1);
            CP_COMMIT();
            asm volatile("cp.async.wait_group 1;");
        } else {
            asm volatile("cp.async.wait_group 0;");
        }
        __syncthreads();

        const uint32_t Ah = sb + (uint32_t)(buf * 49152);
        const uint32_t Al = Ah + 16384u;
        const uint32_t Bh = Ah + 32768u;
        const uint32_t Bl = Bh + 8192u;

        #pragma unroll
        for (int kc = 0; kc < 4; kc++) {
            const uint32_t acol = (uint32_t)(((2 * kc + ahalf) * 16)) ^ aswz;
            const uint32_t bcol = (uint32_t)(((2 * kc + bosel) * 16)) ^ bswz;
            uint32_t ah[2][4], al[2][4], bh[2][4], bl[2][4];
            #pragma unroll
            for (int mt = 0; mt < 2; mt++) {
                uint32_t ro = (uint32_t)((m0 + mt * 16 + arow) * 128);
                LDSM4(ah[mt][0], ah[mt][1], ah[mt][2], ah[mt][3], Ah + ro + acol);
                LDSM4(al[mt][0], al[mt][1], al[mt][2], al[mt][3], Al + ro + acol);
            }
            #pragma unroll
            for (int gp = 0; gp < 2; gp++) {
                uint32_t ro = (uint32_t)((n0 + gp * 16 + brow) * 128);
                LDSM4(bh[gp][0], bh[gp][1], bh[gp][2], bh[gp][3], Bh + ro + bcol);
                LDSM4(bl[gp][0], bl[gp][1], bl[gp][2], bl[gp][3], Bl + ro + bcol);
            }
            #pragma unroll
            for (int mt = 0; mt < 2; mt++)
                #pragma unroll
                for (int t = 0; t < 4; t++) {
                    const int gp = t >> 1, pv = (t & 1) * 2;
                    mma16816(c[mt][t], ah[mt], bh[gp][pv], bh[gp][pv + 1]);
                    mma16816(c[mt][t], ah[mt], bl[gp][pv], bl[gp][pv + 1]);
                    mma16816(c[mt][t], al[mt], bh[gp][pv], bh[gp][pv + 1]);
                }
        }
        __syncthreads();
    }

    const int crow = lane >> 2;
    const int ccol = (lane & 3) * 2;

    if (sel == 2) {
        // ---- V epilogue: bias add -> smem fp32 tile -> transposed split ----
        float (*vt)[65] = (float(*)[65])gsm;   // 128 x 65 floats (33 KB)
        #pragma unroll
        for (int mt = 0; mt < 2; mt++)
            #pragma unroll
            for (int t = 0; t < 4; t++) {
                const int rloc = m0 + mt * 16 + crow;
                const int cloc = n0 + t * 8 + ccol;
                const float b0 = bias[nBase + cloc], b1 = bias[nBase + cloc + 1];
                vt[rloc][cloc]     = c[mt][t][0] + b0;
                vt[rloc][cloc + 1] = c[mt][t][1] + b1;
                vt[rloc + 8][cloc]     = c[mt][t][2] + b0;
                vt[rloc + 8][cloc + 1] = c[mt][t][3] + b1;
            }
        __syncthreads();
        const int b  = mBase / SS;
        const int s0 = mBase % SS;
        const int bh = b * HH + (nBase / HDIM);
        #pragma unroll
        for (int i = 0; i < 16; i++) {
            int p  = tid + i * 256;            // 0..4095
            int dl = p >> 6;                   // dim 0..63
            int pp = p & 63;                   // token pair 0..63
            uint32_t hi, lo;
            split2(make_float2(vt[2 * pp][dl], vt[2 * pp + 1][dl]), hi, lo);
            size_t idx = (size_t)(bh * HDIM + dl) * (SS / 2) + (s0 >> 1) + pp;
            gvt_h[idx] = hi;
            gvt_l[idx] = lo;
        }
    } else {
        const float scale = (sel == 0) ? QSCALE : 1.0f;
        uint32_t* oh = (sel == 0) ? gq_h : gk_h;
        uint32_t* ol = (sel == 0) ? gq_l : gk_l;
        #pragma unroll
        for (int mt = 0; mt < 2; mt++)
            #pragma unroll
            for (int t = 0; t < 4; t++) {
                const int row = mBase + m0 + mt * 16 + crow;
                const int col = nBase + n0 + t * 8 + ccol;
                const float b0 = bias[col], b1 = bias[col + 1];
                float2 v0 = make_float2((c[mt][t][0] + b0) * scale,
                                        (c[mt][t][1] + b1) * scale);
                float2 v1 = make_float2((c[mt][t][2] + b0) * scale,
                                        (c[mt][t][3] + b1) * scale);
                size_t p0 = (size_t)row * 256 + col / 2;
                size_t p1 = (size_t)(row + 8) * 256 + col / 2;
                split2(v0, oh[p0], ol[p0]);
                split2(v1, oh[p1], ol[p1]);
            }
    }
}

// ===========================================================================
// Kernel B: warp-MMA flash attention (128 thr, q-tile 64, no online max,
// single-MUFU ex2.approx with log2e pre-folded into q).
// __launch_bounds__(128,3) pins 3 CTAs/SM (168-reg ceiling).
// ===========================================================================
#define KT 64
#define NT (SS / KT)

__global__ __launch_bounds__(128, 3) void attn_mma_kernel(float* __restrict__ out)
{
    extern __shared__ uint8_t dynsmem[];
    const int tid  = threadIdx.x;
    const int w    = tid >> 5;
    const int lane = tid & 31;
    const int r0   = lane >> 2;
    const int c0   = (lane & 3) * 2;
    const int qt = blockIdx.x, h = blockIdx.y, b = blockIdx.z;
    const int bh = b * HH + h;
    const int qr = qt * 64 + w * 16 + r0;

    const uint32_t smem_base = (uint32_t)__cvta_generic_to_shared(dynsmem);

    uint32_t aQh[4][4], aQl[4][4];
    {
        const size_t row0 = (size_t)(b * SS + qr) * 256 + h * 32;
        const size_t row8 = row0 + 8 * 256;
        #pragma unroll
        for (int kc = 0; kc < 4; kc++) {
            int idx = kc * 8 + (lane & 3);
            aQh[kc][0] = gq_h[row0 + idx];     aQl[kc][0] = gq_l[row0 + idx];
            aQh[kc][1] = gq_h[row8 + idx];     aQl[kc][1] = gq_l[row8 + idx];
            aQh[kc][2] = gq_h[row0 + idx + 4]; aQl[kc][2] = gq_l[row0 + idx + 4];
            aQh[kc][3] = gq_h[row8 + idx + 4]; aQl[kc][3] = gq_l[row8 + idx + 4];
        }
    }

    auto stage = [&](int buf, int t) {
        #pragma unroll
        for (int j = 0; j < 16; j++) {
            const int c = tid + (j & 3) * 128;
            const int arr4 = j >> 2;
            const int r = c >> 3, i = c & 7;
            const uint32_t swz = (uint32_t)((i * 16) ^ ((r & 7) << 4));
            const uint32_t* src;
            uint32_t dst;
            if (arr4 < 2) {
                src = (arr4 == 0 ? gk_h : gk_l) +
                      ((size_t)(b * SS + t * KT + r) * 256 + h * 32 + i * 4);
                dst = smem_base + (uint32_t)((buf * 2 + arr4) * 8192 + r * 128) + swz;
            } else {
                src = (arr4 == 2 ? gvt_h : gvt_l) +
                      ((size_t)(bh * HDIM + r) * (SS/2) + t * 32 + i * 4);
                dst = smem_base + 32768u + (uint32_t)((buf * 2 + (arr4 - 2)) * 8192 + r * 128) + swz;
            }
            CP_ASYNC16(dst, src);
        }
    };

    float o[8][4];
    #pragma unroll
    for (int dt = 0; dt < 8; dt++)
        #pragma unroll
        for (int i = 0; i < 4; i++) o[dt][i] = 0.0f;
    float lA0 = 0.0f, lA1 = 0.0f, lB0 = 0.0f, lB1 = 0.0f;

    const int lrow = ((lane >> 4) << 3) + (lane & 7);
    const int osel = (lane >> 3) & 1;
    const uint32_t lswz = (uint32_t)((lrow & 7) << 4);

    stage(0, 0);
    CP_COMMIT();

    for (int t = 0; t < NT; t++) {
        const int buf = t & 1;
        if (t + 1 < NT) {
            stage(buf ^ 1, t + 1);
            CP_COMMIT();
            asm volatile("cp.async.wait_group 1;");
        } else {
            asm volatile("cp.async.wait_group 0;");
        }
        __syncthreads();

        const uint32_t Kh_b = smem_base + (uint32_t)((buf * 2 + 0) * 8192);
        const uint32_t Kl_b = smem_base + (uint32_t)((buf * 2 + 1) * 8192);
        const uint32_t Vh_b = smem_base + 32768u + (uint32_t)((buf * 2 + 0) * 8192);
        const uint32_t Vl_b = smem_base + 32768u + (uint32_t)((buf * 2 + 1) * 8192);

        // ---- Scores ----
        float sc[8][4];
        #pragma unroll
        for (int gp = 0; gp < 4; gp++) {
            float s0[4] = {0,0,0,0}, s1[4] = {0,0,0,0};
            const uint32_t rbase = (uint32_t)((gp * 16 + lrow) * 128);
            #pragma unroll
            for (int kc = 0; kc < 4; kc++) {
                const uint32_t boff = (uint32_t)(((2*kc + osel) * 16)) ^ lswz;
                uint32_t h0,h1,h2,h3, l0,l1,l2,l3;
                LDSM4(h0,h1,h2,h3, Kh_b + rbase + boff);
                LDSM4(l0,l1,l2,l3, Kl_b + rbase + boff);
                mma16816(s0, aQh[kc], h0, h1);
                mma16816(s0, aQh[kc], l0, l1);
                mma16816(s0, aQl[kc], h0, h1);
                mma16816(s1, aQh[kc], h2, h3);
                mma16816(s1, aQh[kc], l2, l3);
                mma16816(s1, aQl[kc], h2, h3);
            }
            #pragma unroll
            for (int i = 0; i < 4; i++) { sc[2*gp][i] = s0[i]; sc[2*gp+1][i] = s1[i]; }
        }

        // ---- ex2 (single MUFU; log2e folded into q) + dual partial sums ----
        #pragma unroll
        for (int nt = 0; nt < 8; nt++) {
            sc[nt][0] = ex2f(sc[nt][0]); lA0 += sc[nt][0];
            sc[nt][1] = ex2f(sc[nt][1]); lA1 += sc[nt][1];
            sc[nt][2] = ex2f(sc[nt][2]); lB0 += sc[nt][2];
            sc[nt][3] = ex2f(sc[nt][3]); lB1 += sc[nt][3];
        }

        // ---- Repack P into A-fragments (hi/lo) ----
        uint32_t aPh[4][4], aPl[4][4];
        #pragma unroll
        for (int kc = 0; kc < 4; kc++) {
            split2(make_float2(sc[2*kc  ][0], sc[2*kc  ][1]), aPh[kc][0], aPl[kc][0]);
            split2(make_float2(sc[2*kc  ][2], sc[2*kc  ][3]), aPh[kc][1], aPl[kc][1]);
            split2(make_float2(sc[2*kc+1][0], sc[2*kc+1][1]), aPh[kc][2], aPl[kc][2]);
            split2(make_float2(sc[2*kc+1][2], sc[2*kc+1][3]), aPh[kc][3], aPl[kc][3]);
        }

        // ---- O += P*V ----
        #pragma unroll
        for (int dtp = 0; dtp < 4; dtp++) {
            const uint32_t rbase = (uint32_t)((dtp * 16 + lrow) * 128);
            #pragma unroll
            for (int kc = 0; kc < 4; kc++) {
                const uint32_t boff = (uint32_t)(((2*kc + osel) * 16)) ^ lswz;
                uint32_t v0,v1,v2,v3, w0,w1,w2,w3;
                LDSM4(v0,v1,v2,v3, Vh_b + rbase + boff);
                LDSM4(w0,w1,w2,w3, Vl_b + rbase + boff);
                mma16816(o[2*dtp],   aPh[kc], v0, v1);
                mma16816(o[2*dtp],   aPh[kc], w0, w1);
                mma16816(o[2*dtp],   aPl[kc], v0, v1);
                mma16816(o[2*dtp+1], aPh[kc], v2, v3);
                mma16816(o[2*dtp+1], aPh[kc], w2, w3);
                mma16816(o[2*dtp+1], aPl[kc], v2, v3);
            }
        }
        __syncthreads();
    }

    // ---- Final l reduction across the quad, then normalize + store ----
    float lA = lA0 + lA1, lB = lB0 + lB1;
    lA += __shfl_xor_sync(0xffffffff, lA, 1);
    lA += __shfl_xor_sync(0xffffffff, lA, 2);
    lB += __shfl_xor_sync(0xffffffff, lB, 1);
    lB += __shfl_xor_sync(0xffffffff, lB, 2);
    const float ivA = 1.0f / lA, ivB = 1.0f / lB;
    #pragma unroll
    for (int dt = 0; dt < 8; dt++) {
        float2 t0 = make_float2(o[dt][0] * ivA, o[dt][1] * ivA);
        float2 t1 = make_float2(o[dt][2] * ivB, o[dt][3] * ivB);
        *(float2*)&out[((size_t)(b*SS + qr    ))*DD + h*HDIM + dt*8 + c0] = t0;
        *(float2*)&out[((size_t)(b*SS + qr + 8))*DD + h*HDIM + dt*8 + c0] = t1;
    }
}

// ===========================================================================
extern "C" void kernel_launch(void* const* d_in, const int* in_sizes, int n_in,
                              void* d_out, int out_size)
{
    const float* x  = (const float*)d_in[0];
    const float* Wq = (const float*)d_in[1];
    const float* bq = (const float*)d_in[2];
    const float* Wk = (const float*)d_in[3];
    const float* bk = (const float*)d_in[4];
    const float* Wv = (const float*)d_in[5];
    const float* bv = (const float*)d_in[6];
    float* out = (float*)d_out;

    split_x_kernel<<<MTOT * DD / 4 / 256, 256>>>(x);
    split_w_kernel<<<dim3(DD * DD / 4 / 256, 3), 256>>>(Wq, Wk, Wv);

    cudaFuncSetAttribute(qkv_mma_gemm_kernel,
                         cudaFuncAttributeMaxDynamicSharedMemorySize, 98304);
    dim3 gg(DD / GBN, MTOT / GBM, 3);
    qkv_mma_gemm_kernel<<<gg, 256, 98304>>>(bq, bk, bv);

    cudaFuncSetAttribute(attn_mma_kernel,
                         cudaFuncAttributeMaxDynamicSharedMemorySize, 65536);
    dim3 g2(SS / 64, HH, BB);
    attn_mma_kernel<<<g2, 128, 65536>>>(out);
}